// round 1
// baseline (speedup 1.0000x reference)
#include <cuda_runtime.h>

#define BATCH  8
#define HWDIM  64
#define CCH    256
#define RED    64
#define EE     144     // K*K*G = 9*16
#define TILE   8

// SMEM layout (float offsets)
#define XH_STRIDE  260                 // 256 + 4 pad (bank spread)
#define OFF_XH     0                   // 100 * 260 = 26000
#define OFF_W1     26000               // 256*64 = 16384   (reused as WGT after stage1)
#define OFF_WGT    26000               // 64*144 = 9216
#define OFF_W2     42384               // 64*144 = 9216
#define OFF_MID    51600               // 64*68 = 4352
#define MID_STRIDE 68
#define SMEM_FLOATS 55952
#define SMEM_BYTES (SMEM_FLOATS * 4)   // 223808 B < 227KB limit

__global__ void __launch_bounds__(256, 1)
invo_fused_kernel(const float* __restrict__ x,
                  const float* __restrict__ W1,
                  const float* __restrict__ b1,
                  const float* __restrict__ W2,
                  const float* __restrict__ b2,
                  float* __restrict__ out)
{
    extern __shared__ float s[];
    const int t  = threadIdx.x;
    const int bb = blockIdx.z;
    const int h0 = blockIdx.y * TILE;
    const int w0 = blockIdx.x * TILE;

    // ---- Phase 0: load 10x10 halo tile of x (zero-padded), W1, W2 ----
    #pragma unroll
    for (int it = 0; it < 25; it++) {
        int i4 = t + it * 256;             // 0..6399 float4s
        int c4 = i4 & 63;                  // 64 float4 per spatial pos
        int sp = i4 >> 6;                  // 0..99
        int r  = sp / 10;
        int cl = sp - r * 10;
        int gh = h0 - 1 + r;
        int gw = w0 - 1 + cl;
        float4 v = make_float4(0.f, 0.f, 0.f, 0.f);
        if ((unsigned)gh < HWDIM && (unsigned)gw < HWDIM)
            v = *(const float4*)(x + ((size_t)((bb * HWDIM + gh) * HWDIM + gw) * CCH) + c4 * 4);
        *(float4*)(s + OFF_XH + sp * XH_STRIDE + c4 * 4) = v;
    }
    #pragma unroll
    for (int it = 0; it < 16; it++) {      // W1: 256x64 = 4096 float4
        int i4 = t + it * 256;
        *(float4*)(s + OFF_W1 + i4 * 4) = *(const float4*)(W1 + i4 * 4);
    }
    #pragma unroll
    for (int it = 0; it < 9; it++) {       // W2: 64x144 = 2304 float4
        int i4 = t + it * 256;
        *(float4*)(s + OFF_W2 + i4 * 4) = *(const float4*)(W2 + i4 * 4);
    }
    __syncthreads();

    const int tm = t >> 4;   // 0..15 : pixel group (4 px each)
    const int tn = t & 15;   // 0..15 : N group

    // ---- Stage 1: mid[64px][64] = x_tile @ W1 + b1 ----
    {
        float acc[4][4];
        #pragma unroll
        for (int j = 0; j < 4; j++) {
            float bv = __ldg(b1 + tn * 4 + j);
            #pragma unroll
            for (int i = 0; i < 4; i++) acc[i][j] = bv;
        }
        int spb[4];
        #pragma unroll
        for (int i = 0; i < 4; i++) {
            int px = tm * 4 + i;
            spb[i] = OFF_XH + (((px >> 3) + 1) * 10 + (px & 7) + 1) * XH_STRIDE;
        }
        for (int k = 0; k < CCH; k += 4) {
            float4 xa[4];
            #pragma unroll
            for (int i = 0; i < 4; i++)
                xa[i] = *(const float4*)(s + spb[i] + k);
            #pragma unroll
            for (int kk = 0; kk < 4; kk++) {
                float4 wv = *(const float4*)(s + OFF_W1 + (k + kk) * RED + tn * 4);
                #pragma unroll
                for (int i = 0; i < 4; i++) {
                    float xv = (kk == 0) ? xa[i].x : (kk == 1) ? xa[i].y : (kk == 2) ? xa[i].z : xa[i].w;
                    acc[i][0] += xv * wv.x;
                    acc[i][1] += xv * wv.y;
                    acc[i][2] += xv * wv.z;
                    acc[i][3] += xv * wv.w;
                }
            }
        }
        #pragma unroll
        for (int i = 0; i < 4; i++)
            *(float4*)(s + OFF_MID + (tm * 4 + i) * MID_STRIDE + tn * 4) =
                make_float4(acc[i][0], acc[i][1], acc[i][2], acc[i][3]);
    }
    __syncthreads();

    // ---- Stage 2: wgt[64px][144] = mid @ W2 + b2  (stored over W1 region) ----
    {
        float acc[4][9];
        #pragma unroll
        for (int j = 0; j < 9; j++) {
            float bv = __ldg(b2 + tn * 9 + j);
            #pragma unroll
            for (int i = 0; i < 4; i++) acc[i][j] = bv;
        }
        for (int d = 0; d < RED; d += 4) {
            float4 ma[4];
            #pragma unroll
            for (int i = 0; i < 4; i++)
                ma[i] = *(const float4*)(s + OFF_MID + (tm * 4 + i) * MID_STRIDE + d);
            #pragma unroll
            for (int dd = 0; dd < 4; dd++) {
                float wv[9];
                #pragma unroll
                for (int j = 0; j < 9; j++)
                    wv[j] = s[OFF_W2 + (d + dd) * EE + tn * 9 + j];
                #pragma unroll
                for (int i = 0; i < 4; i++) {
                    float xv = (dd == 0) ? ma[i].x : (dd == 1) ? ma[i].y : (dd == 2) ? ma[i].z : ma[i].w;
                    #pragma unroll
                    for (int j = 0; j < 9; j++)
                        acc[i][j] += xv * wv[j];
                }
            }
        }
        #pragma unroll
        for (int i = 0; i < 4; i++)
            #pragma unroll
            for (int j = 0; j < 9; j++)
                s[OFF_WGT + (tm * 4 + i) * EE + tn * 9 + j] = acc[i][j];
    }
    __syncthreads();

    // ---- Stage 3: involution ----
    // out[px, ch=g*16+gc] = sum_k wgt[px, g*9+k] * xpad[px + off(ko), ch_src]
    // with f = g*144 + gc*9 + k, ko = f>>8 (spatial tap), ch_src = f&255.
    {
        const int warp = t >> 5;
        const int lane = t & 31;
        const int pr = warp;                                 // tile row (8 warps)
        const int wgt_row = OFF_WGT + pr * 8 * EE;
        const int xrow = OFF_XH + pr * 10 * XH_STRIDE;       // halo row pr == tap di=0 of interior row pr
        const size_t outrow = (size_t)((bb * HWDIM + h0 + pr) * HWDIM + w0) * CCH;
        #pragma unroll
        for (int j = 0; j < 8; j++) {
            int ch  = lane + 32 * j;
            int g   = ch >> 4;
            int gc  = ch & 15;
            int f0  = g * EE + gc * 9;
            int ko0 = f0 >> 8;
            int cs0 = f0 & 255;
            int tc  = 256 - cs0;                 // #taps before crossing a 256 boundary
            int di0 = (ko0 * 86) >> 8;           // ko0 / 3
            int dj0 = ko0 - 3 * di0;
            int ko1 = ko0 + 1;
            int di1 = (ko1 * 86) >> 8;
            int dj1 = ko1 - 3 * di1;
            int off0 = (di0 * 10 + dj0) * XH_STRIDE + cs0;
            int off1 = (di1 * 10 + dj1) * XH_STRIDE;
            int wbase = wgt_row + g * 9;
            #pragma unroll
            for (int pc = 0; pc < 8; pc++) {
                int bx = xrow + pc * XH_STRIDE;
                int A0 = bx + off0;              // addr = A0 + k          (k <  tc)
                int A1 = bx + off1 - tc;         // addr = A1 + k          (k >= tc)
                float acc = 0.f;
                #pragma unroll
                for (int k = 0; k < 9; k++) {
                    float wv = s[wbase + pc * EE + k];
                    int addr = (k < tc) ? (A0 + k) : (A1 + k);
                    acc += wv * s[addr];
                }
                out[outrow + pc * CCH + ch] = acc;
            }
        }
    }
}

extern "C" void kernel_launch(void* const* d_in, const int* in_sizes, int n_in,
                              void* d_out, int out_size)
{
    (void)in_sizes; (void)n_in; (void)out_size;
    const float* x  = (const float*)d_in[0];
    const float* W1 = (const float*)d_in[1];
    const float* b1 = (const float*)d_in[2];
    const float* W2 = (const float*)d_in[3];
    const float* b2 = (const float*)d_in[4];
    float* out = (float*)d_out;

    cudaFuncSetAttribute(invo_fused_kernel,
                         cudaFuncAttributeMaxDynamicSharedMemorySize, SMEM_BYTES);
    dim3 grid(HWDIM / TILE, HWDIM / TILE, BATCH);   // (8, 8, 8) = 512 CTAs
    invo_fused_kernel<<<grid, 256, SMEM_BYTES>>>(x, W1, b1, W2, b2, out);
}

// round 2
// speedup vs baseline: 1.4050x; 1.4050x over previous
#include <cuda_runtime.h>

#define BATCH  8
#define HWDIM  64
#define CCH    256
#define RED    64
#define EE     144     // K*K*G = 9*16
#define TILE   8
#define NTHR   512

// SMEM layout (float offsets)
#define XH_STRIDE  260                 // 256 + 4 pad
#define OFF_XH     0                   // 100 * 260 = 26000
#define OFF_W1     26000               // 256*64 = 16384   (reused as WGT after stage1)
#define OFF_WGT    26000               // 64*144 = 9216
#define OFF_W2     42384               // 64*144 = 9216
#define OFF_MID    51600               // 64*68 = 4352
#define MID_STRIDE 68
#define SMEM_FLOATS 55952
#define SMEM_BYTES (SMEM_FLOATS * 4)   // 223808 B < 227KB limit

__global__ void __launch_bounds__(NTHR, 1)
invo_fused_kernel(const float* __restrict__ x,
                  const float* __restrict__ W1,
                  const float* __restrict__ b1,
                  const float* __restrict__ W2,
                  const float* __restrict__ b2,
                  float* __restrict__ out)
{
    extern __shared__ float s[];
    const int t  = threadIdx.x;
    const int bb = blockIdx.z;
    const int h0 = blockIdx.y * TILE;
    const int w0 = blockIdx.x * TILE;

    // ---- Phase 0: load 10x10 halo tile of x (zero-padded), W1, W2 ----
    #pragma unroll
    for (int it = 0; it < 13; it++) {
        int i4 = t + it * NTHR;            // 0..6399 float4s
        if (i4 < 6400) {
            int c4 = i4 & 63;              // 64 float4 per spatial pos
            int sp = i4 >> 6;              // 0..99
            int r  = sp / 10;
            int cl = sp - r * 10;
            int gh = h0 - 1 + r;
            int gw = w0 - 1 + cl;
            float4 v = make_float4(0.f, 0.f, 0.f, 0.f);
            if ((unsigned)gh < HWDIM && (unsigned)gw < HWDIM)
                v = *(const float4*)(x + ((size_t)((bb * HWDIM + gh) * HWDIM + gw) * CCH) + c4 * 4);
            *(float4*)(s + OFF_XH + sp * XH_STRIDE + c4 * 4) = v;
        }
    }
    #pragma unroll
    for (int it = 0; it < 8; it++) {       // W1: 256x64 = 4096 float4
        int i4 = t + it * NTHR;
        *(float4*)(s + OFF_W1 + i4 * 4) = *(const float4*)(W1 + i4 * 4);
    }
    #pragma unroll
    for (int it = 0; it < 5; it++) {       // W2: 64x144 = 2304 float4
        int i4 = t + it * NTHR;
        if (i4 < 2304)
            *(float4*)(s + OFF_W2 + i4 * 4) = *(const float4*)(W2 + i4 * 4);
    }
    __syncthreads();

    const int tm = t >> 4;   // 0..31 : pixel pair index (2 px each)
    const int tn = t & 15;   // 0..15

    // ---- Stage 1: mid[64px][64] = x_tile @ W1 + b1  (2px x 4n per thread) ----
    {
        float acc[2][4];
        {
            float4 bv = *(const float4*)(b1 + tn * 4);
            acc[0][0] = bv.x; acc[0][1] = bv.y; acc[0][2] = bv.z; acc[0][3] = bv.w;
            acc[1][0] = bv.x; acc[1][1] = bv.y; acc[1][2] = bv.z; acc[1][3] = bv.w;
        }
        int spb[2];
        #pragma unroll
        for (int i = 0; i < 2; i++) {
            int px = tm * 2 + i;
            spb[i] = OFF_XH + (((px >> 3) + 1) * 10 + (px & 7) + 1) * XH_STRIDE;
        }
        #pragma unroll 4
        for (int k = 0; k < CCH; k += 4) {
            float4 xa[2];
            xa[0] = *(const float4*)(s + spb[0] + k);
            xa[1] = *(const float4*)(s + spb[1] + k);
            #pragma unroll
            for (int kk = 0; kk < 4; kk++) {
                float4 wv = *(const float4*)(s + OFF_W1 + (k + kk) * RED + tn * 4);
                #pragma unroll
                for (int i = 0; i < 2; i++) {
                    float xv = (kk == 0) ? xa[i].x : (kk == 1) ? xa[i].y : (kk == 2) ? xa[i].z : xa[i].w;
                    acc[i][0] += xv * wv.x;
                    acc[i][1] += xv * wv.y;
                    acc[i][2] += xv * wv.z;
                    acc[i][3] += xv * wv.w;
                }
            }
        }
        #pragma unroll
        for (int i = 0; i < 2; i++)
            *(float4*)(s + OFF_MID + (tm * 2 + i) * MID_STRIDE + tn * 4) =
                make_float4(acc[i][0], acc[i][1], acc[i][2], acc[i][3]);
    }
    __syncthreads();

    // ---- Stage 2: wgt[64px][144] = mid @ W2 + b2  (2px x 9e per thread; over W1) ----
    {
        float acc[2][9];
        #pragma unroll
        for (int j = 0; j < 9; j++) {
            float bv = __ldg(b2 + tn * 9 + j);
            acc[0][j] = bv;
            acc[1][j] = bv;
        }
        #pragma unroll 4
        for (int d = 0; d < RED; d += 4) {
            float4 ma[2];
            ma[0] = *(const float4*)(s + OFF_MID + (tm * 2 + 0) * MID_STRIDE + d);
            ma[1] = *(const float4*)(s + OFF_MID + (tm * 2 + 1) * MID_STRIDE + d);
            #pragma unroll
            for (int dd = 0; dd < 4; dd++) {
                float wv[9];
                #pragma unroll
                for (int j = 0; j < 9; j++)
                    wv[j] = s[OFF_W2 + (d + dd) * EE + tn * 9 + j];
                #pragma unroll
                for (int i = 0; i < 2; i++) {
                    float xv = (dd == 0) ? ma[i].x : (dd == 1) ? ma[i].y : (dd == 2) ? ma[i].z : ma[i].w;
                    #pragma unroll
                    for (int j = 0; j < 9; j++)
                        acc[i][j] += xv * wv[j];
                }
            }
        }
        #pragma unroll
        for (int i = 0; i < 2; i++)
            #pragma unroll
            for (int j = 0; j < 9; j++)
                s[OFF_WGT + (tm * 2 + i) * EE + tn * 9 + j] = acc[i][j];
    }
    __syncthreads();

    // ---- Stage 3: involution (16 warps: 8 tile rows x 2 channel halves) ----
    // out[px, ch=g*16+gc] = sum_k wgt[px, g*9+k] * xpad[px + off(ko), ch_src]
    // with f = g*144 + gc*9 + k, ko = f>>8 (spatial tap), ch_src = f&255.
    {
        const int warp = t >> 5;
        const int lane = t & 31;
        const int pr   = warp >> 1;                          // tile row 0..7
        const int half = warp & 1;                           // channel half
        const int wgt_row = OFF_WGT + pr * 8 * EE;
        const int xrow = OFF_XH + pr * 10 * XH_STRIDE;       // halo row pr == tap di=0 of interior row pr
        const size_t outrow = (size_t)((bb * HWDIM + h0 + pr) * HWDIM + w0) * CCH;
        #pragma unroll
        for (int j = 0; j < 4; j++) {
            int ch  = lane + 32 * (half * 4 + j);
            int g   = ch >> 4;
            int gc  = ch & 15;
            int f0  = g * EE + gc * 9;
            int ko0 = f0 >> 8;
            int cs0 = f0 & 255;
            int tc  = 256 - cs0;                 // #taps before crossing a 256 boundary
            int di0 = (ko0 * 86) >> 8;           // ko0 / 3
            int dj0 = ko0 - 3 * di0;
            int ko1 = ko0 + 1;
            int di1 = (ko1 * 86) >> 8;
            int dj1 = ko1 - 3 * di1;
            int off0 = (di0 * 10 + dj0) * XH_STRIDE + cs0;
            int off1 = (di1 * 10 + dj1) * XH_STRIDE;
            int wbase = wgt_row + g * 9;
            #pragma unroll
            for (int pc = 0; pc < 8; pc++) {
                int bx = xrow + pc * XH_STRIDE;
                int A0 = bx + off0;              // addr = A0 + k          (k <  tc)
                int A1 = bx + off1 - tc;         // addr = A1 + k          (k >= tc)
                float acc = 0.f;
                #pragma unroll
                for (int k = 0; k < 9; k++) {
                    float wv = s[wbase + pc * EE + k];
                    int addr = (k < tc) ? (A0 + k) : (A1 + k);
                    acc += wv * s[addr];
                }
                out[outrow + pc * CCH + ch] = acc;
            }
        }
    }
}

extern "C" void kernel_launch(void* const* d_in, const int* in_sizes, int n_in,
                              void* d_out, int out_size)
{
    (void)in_sizes; (void)n_in; (void)out_size;
    const float* x  = (const float*)d_in[0];
    const float* W1 = (const float*)d_in[1];
    const float* b1 = (const float*)d_in[2];
    const float* W2 = (const float*)d_in[3];
    const float* b2 = (const float*)d_in[4];
    float* out = (float*)d_out;

    cudaFuncSetAttribute(invo_fused_kernel,
                         cudaFuncAttributeMaxDynamicSharedMemorySize, SMEM_BYTES);
    dim3 grid(HWDIM / TILE, HWDIM / TILE, BATCH);   // (8, 8, 8) = 512 CTAs
    invo_fused_kernel<<<grid, NTHR, SMEM_BYTES>>>(x, W1, b1, W2, b2, out);
}